// round 1
// baseline (speedup 1.0000x reference)
#include <cuda_runtime.h>
#include <cstdint>

// Lookahead depthwise conv:
//   out[s,b,f] = sum_{k=0..20} x[s+k,b,f] * weight[f,k]   (x[t>=S] := 0)
// x, out: (S=2048, B=32, F=1024) fp32, contiguous (f fastest, then b, then s).
// weight: (F=1024, 21) fp32.
//
// Strategy: register sliding window per (b, f-pair) column, streaming s.
// Each thread owns 2 adjacent f lanes (float2 / 64-bit loads+stores) and a
// chunk of 512 s-steps. Window ring of 21 float2 in registers; s-loop is
// unrolled in groups of 21 so all ring indices are compile-time. Math uses
// the Blackwell packed fma.rn.f32x2 pipe (2 fp32 FMAs per issue slot) to keep
// the FMA pipe off the critical path; the kernel is then purely HBM-streaming
// with exactly 1 read + 1 write per element.

#define S_LEN   2048
#define BATCH   32
#define NFEAT   1024
#define CTX1    21                      // CONTEXT + 1
#define NCOL2   ((BATCH * NFEAT) / 2)   // 16384 float2 columns per s-slab
#define NCHUNK  4
#define CHUNK   (S_LEN / NCHUNK)        // 512

typedef unsigned long long u64;

__device__ __forceinline__ u64 fma2(u64 a, u64 b, u64 c) {
    u64 d;
    asm("fma.rn.f32x2 %0, %1, %2, %3;" : "=l"(d) : "l"(a), "l"(b), "l"(c));
    return d;
}
__device__ __forceinline__ u64 mul2(u64 a, u64 b) {
    u64 d;
    asm("mul.rn.f32x2 %0, %1, %2;" : "=l"(d) : "l"(a), "l"(b));
    return d;
}

__global__ __launch_bounds__(256, 2)
void lookahead_kernel(const u64* __restrict__ x,
                      const float* __restrict__ w,
                      u64* __restrict__ out)
{
    const int gid   = blockIdx.x * 256 + threadIdx.x;
    const int col   = gid & (NCOL2 - 1);     // float2 column within a slab
    const int chunk = gid >> 14;             // gid / NCOL2, 0..3
    const int s_begin = chunk * CHUNK;
    const int s_end   = s_begin + CHUNK;
    // last x row this chunk ever needs: s_end-1+20 (clamped to S)
    const int t_max = (s_end + CTX1 - 1 < S_LEN) ? (s_end + CTX1 - 1) : S_LEN;

    // ---- per-thread packed weights: lane f0 in low word, f0+1 in high word
    const int f0 = (col << 1) & (NFEAT - 1);
    const float* wr = w + f0 * CTX1;
    u64 wk[CTX1];
    #pragma unroll
    for (int k = 0; k < CTX1; ++k) {
        float lo = __ldg(wr + k);            // weight[f0][k]
        float hi = __ldg(wr + CTX1 + k);     // weight[f0+1][k]
        wk[k] = ((u64)__float_as_uint(hi) << 32) | (u64)__float_as_uint(lo);
    }

    const u64* xp = x + col;
    u64*       op = out + col;

    // ---- prologue: window holds x[s_begin .. s_begin+20]
    // slot(t) = t % 21; s_begin is a multiple of... not of 21, but we define
    // slot relative to s_begin: slot j holds x[s_begin + j + m*21].
    u64 win[CTX1];
    #pragma unroll
    for (int j = 0; j < CTX1; ++j)
        win[j] = xp[(size_t)(s_begin + j) * NCOL2];   // s_begin+20 <= 1556 < S, safe

    // ---- main loop: s advances by 21 per outer iter; inner fully unrolled so
    // ring indices are constants (no register shuffling / spills).
    for (int s0 = s_begin; s0 < s_end; s0 += CTX1) {
        #pragma unroll
        for (int p = 0; p < CTX1; ++p) {
            const int s = s0 + p;
            // window invariant: win[(p + k) % 21] == x[s + k]
            u64 acc = mul2(wk[0], win[p]);
            #pragma unroll
            for (int k = 1; k < CTX1; ++k) {
                int slot = p + k;
                if (slot >= CTX1) slot -= CTX1;      // compile-time after unroll
                acc = fma2(wk[k], win[slot], acc);
            }
            if (s < s_end)
                op[(size_t)s * NCOL2] = acc;

            // fetch x[s+21] into the slot just vacated by x[s]
            const int t = s + CTX1;
            u64 v = 0ull;
            if (t < t_max)
                v = xp[(size_t)t * NCOL2];
            win[p] = v;
        }
    }
}

extern "C" void kernel_launch(void* const* d_in, const int* in_sizes, int n_in,
                              void* d_out, int out_size)
{
    const u64*   x = (const u64*)d_in[0];     // x: (2048, 32, 1024) fp32
    const float* w = (const float*)d_in[1];   // weight: (1024, 21) fp32
    u64*         o = (u64*)d_out;

    const int total_threads = NCOL2 * NCHUNK;        // 65536
    lookahead_kernel<<<total_threads / 256, 256>>>(x, w, o);
}

// round 2
// speedup vs baseline: 1.0197x; 1.0197x over previous
#include <cuda_runtime.h>
#include <cstdint>

// Lookahead depthwise conv, output-stationary form:
//   out[s,b,f] = sum_{k=0..20} x[s+k,b,f] * weight[f,k]   (x[t>=S] := 0)
// x, out: (S=2048, B=32, F=1024) fp32 contiguous; weight: (1024, 21) fp32.
//
// Each thread owns 2 adjacent f lanes (f32x2) and a chunk of 512 s-steps.
// It holds 21 packed accumulators (one per in-flight output) and streams one
// input row x[t] per step:   acc[(t-k) mod 21] += x[t] * w[k]   (k=0 is MUL,
// which initializes the slot). One finished output retires per step.
// Inputs are prefetched through a 7-deep register FIFO (7 | 21, so all ring
// indices are compile-time constants under the 21-step unroll) giving 7
// outstanding 256B warp-loads -> ~3.7 MB chip-wide in flight = BW*latency.
// All 21 FMAs per step are independent (distinct acc slots): no dep chain.

#define S_LEN   2048
#define NFEAT   1024
#define CTX1    21                      // CONTEXT + 1
#define NCOL2   16384                   // (32*1024)/2 float2 columns per s-slab
#define NCHUNK  4
#define CHUNK   (S_LEN / NCHUNK)        // 512
#define FIFO_D  7

typedef unsigned long long u64;

__device__ __forceinline__ u64 fma2(u64 a, u64 b, u64 c) {
    u64 d;
    asm("fma.rn.f32x2 %0, %1, %2, %3;" : "=l"(d) : "l"(a), "l"(b), "l"(c));
    return d;
}
__device__ __forceinline__ u64 mul2(u64 a, u64 b) {
    u64 d;
    asm("mul.rn.f32x2 %0, %1, %2;" : "=l"(d) : "l"(a), "l"(b));
    return d;
}

__global__ __launch_bounds__(256, 2)
void lookahead_kernel(const u64* __restrict__ x,
                      const float* __restrict__ w,
                      u64* __restrict__ out)
{
    const int gid   = blockIdx.x * 256 + threadIdx.x;
    const int col   = gid & (NCOL2 - 1);
    const int chunk = gid >> 14;                  // 0..3
    const int s_begin = chunk * CHUNK;

    // loads of x[s_begin + rel] are valid while rel < rel_load_max
    int rlm = CHUNK + CTX1 - 1;                   // 532
    if (s_begin + rlm > S_LEN) rlm = S_LEN - s_begin;   // last chunk: 512
    const int rel_load_max = rlm;
    const int rel_total    = CHUNK + CTX1 - 1;    // 532: steps 0..531 do work

    // ---- per-thread packed weights (lane f0 low word, f0+1 high word)
    const int f0 = (col << 1) & (NFEAT - 1);
    const float* wr = w + f0 * CTX1;
    u64 wk[CTX1];
    #pragma unroll
    for (int k = 0; k < CTX1; ++k) {
        float lo = __ldg(wr + k);
        float hi = __ldg(wr + CTX1 + k);
        wk[k] = ((u64)__float_as_uint(hi) << 32) | (u64)__float_as_uint(lo);
    }

    const u64* xp = x   + col + (size_t)s_begin * NCOL2;   // indexed by rel
    u64*       op = out + col + (size_t)s_begin * NCOL2;

    // ---- prime the load FIFO with x[rel = 0..6] (always in-bounds)
    u64 fifo[FIFO_D];
    #pragma unroll
    for (int j = 0; j < FIFO_D; ++j)
        fifo[j] = xp[(size_t)j * NCOL2];

    u64 acc[CTX1];

    // 26 blocks of 21 steps = 546 >= 532; trailing pad steps are fully guarded.
    for (int r0 = 0; r0 < 546; r0 += CTX1) {
        #pragma unroll
        for (int p = 0; p < CTX1; ++p) {
            const int rel = r0 + p;

            // consume this step's input, immediately issue the load 7 ahead
            u64 v  = fifo[p % FIFO_D];
            u64 nv = 0ull;
            const int tl = rel + FIFO_D;
            if (tl < rel_load_max)
                nv = xp[(size_t)tl * NCOL2];
            fifo[p % FIFO_D] = nv;

            // 21 independent packed FMAs; k=0 MUL initializes slot p
            acc[p] = mul2(wk[0], v);
            #pragma unroll
            for (int k = 1; k < CTX1; ++k) {
                int slot = p - k;
                if (slot < 0) slot += CTX1;       // compile-time after unroll
                acc[slot] = fma2(wk[k], v, acc[slot]);
            }

            // output s = rel - 20 completed this step; its slot is (p+1)%21
            if (rel >= CTX1 - 1 && rel < rel_total)
                op[(size_t)(rel - (CTX1 - 1)) * NCOL2] = acc[(p + 1) % CTX1];
        }
    }
}

extern "C" void kernel_launch(void* const* d_in, const int* in_sizes, int n_in,
                              void* d_out, int out_size)
{
    const u64*   x = (const u64*)d_in[0];
    const float* w = (const float*)d_in[1];
    u64*         o = (u64*)d_out;

    lookahead_kernel<<<(NCOL2 * NCHUNK) / 256, 256>>>(x, w, o);
}